// round 5
// baseline (speedup 1.0000x reference)
#include <cuda_runtime.h>
#include <math.h>

#define NLAT  128
#define NLON  256
#define LMAX  50
#define MMAX  50
#define BATCH 2
#define NPTS  2048
#define MGRID (NLAT*NLON)
#define PI_F  3.14159265358979323846f

// bin grid over point domain [-pi,pi] x [-pi,0]
#define BINX 32
#define BINY 16
#define NBIN (BINX*BINY)
#define HX (2.0f*PI_F/(float)BINX)   // pi/16
#define HY (PI_F/(float)BINY)        // pi/16
#define X0 (-PI_F)
#define Y0 (-PI_F)

// Scratch (allocation-free rule: __device__ globals)
__device__ float4 g_pack[BATCH*NPTS];            // phi, theta-pi, s2, rho
__device__ float  g_W[MMAX][NLAT][LMAX];         // legendre*ccw, k-major
__device__ float  g_ft[BATCH][NLON][NLAT];       // interpolated grid, TRANSPOSED

// fast-math helpers (explicit so the rest of the file stays precise)
__device__ __forceinline__ float f_rcp(float v)  { float r; asm("rcp.approx.f32 %0,%1;"  : "=f"(r) : "f"(v)); return r; }
__device__ __forceinline__ float f_rsqrt(float v){ float r; asm("rsqrt.approx.f32 %0,%1;": "=f"(r) : "f"(v)); return r; }
__device__ __forceinline__ float f_div(float a, float b){ float r; asm("div.approx.f32 %0,%1,%2;" : "=f"(r) : "f"(a), "f"(b)); return r; }

// ---------------------------------------------------------------------------
// Kernel 1 (fused): blocks [0,16): cart->spherical; blocks [16,66): weights
// ---------------------------------------------------------------------------
__global__ void k_init(const float* __restrict__ tgt) {
    int blk = blockIdx.x;
    int t   = threadIdx.x;
    if (blk < 16) {
        int i = blk * 256 + t;
        float x = tgt[3*i + 0];
        float y = tgt[3*i + 1];
        float z = tgt[3*i + 2];
        float rho = sqrtf(x*x + y*y + z*z);
        float phi = atan2f(y, x);
        float th  = acosf(z / rho) - PI_F;
        float s2  = phi*phi + th*th;
        g_pack[i] = make_float4(phi, th, s2, rho);
        return;
    }
    if (t >= NLAT) return;
    int m = blk - 16;
    int k = t;
    float tfrac = (float)k * (1.0f / 127.0f);      // theta / pi
    float x = cospif(tfrac);
    float s = sinpif(tfrac);

    // Clenshaw-Curtis weight: S = sum_{kk=1}^{63} 2/(4kk^2-1) cos(2 theta kk)
    // cos(2 theta kk) by Chebyshev recurrence from c1 = cos(2 theta)
    float c1 = cospif(2.0f * tfrac);
    float cprev = 1.0f, ccur = c1;
    float S = 0.0f;
    #pragma unroll 7
    for (int kk = 1; kk <= 63; kk++) {
        float coef = 2.0f * f_rcp((float)(4*kk*kk - 1));
        S = fmaf(coef, ccur, S);
        float cnext = fmaf(2.0f * c1, ccur, -cprev);
        cprev = ccur; ccur = cnext;
    }
    float w = (2.0f / 127.0f) * (1.0f - S);
    if (k == 0 || k == NLAT - 1) w *= 0.5f;

    // P_m^m = sqrt( prod (2j+1)/(2j) / (4pi) ) * (-s)^m
    float pr = 1.0f, sm = 1.0f;
    for (int mm = 1; mm <= m; mm++) {
        pr *= f_div((float)(2*mm + 1), (float)(2*mm));
        sm *= -s;
    }
    float arg = pr * (1.0f / (4.0f * PI_F));
    float pmm = arg * f_rsqrt(arg) * sm;           // sqrt(arg)*sm

    for (int l = 0; l < m; l++) g_W[m][k][l] = 0.0f;
    g_W[m][k][m] = pmm * w;

    if (m + 1 < LMAX) {
        // a(l) = sqrt((4l^2-1)/(l^2-m^2));  bb(l) = 1/a(l-1)
        float ratio = (float)(2*m + 3);            // a(m+1)^2
        float rs    = f_rsqrt(ratio);
        float p2 = pmm;
        float p1 = (ratio * rs) * x * pmm;         // sqrt(2m+3)*x*pmm
        g_W[m][k][m+1] = p1 * w;
        float inva_prev = rs;
        for (int l = m + 2; l < LMAX; l++) {
            float num = (float)(4*l*l - 1);
            float den = (float)(l*l - m*m);
            float rt  = f_div(num, den);
            float r2  = f_rsqrt(rt);
            float a   = rt * r2;                   // sqrt(rt)
            float p   = a * (x * p1 - inva_prev * p2);
            g_W[m][k][l] = p * w;
            p2 = p1; p1 = p; inva_prev = r2;
        }
    }
}

// ---------------------------------------------------------------------------
// Kernel 2: binned 3-NN with per-cell rect pruning + domain-aware termination
// ---------------------------------------------------------------------------
__device__ __forceinline__ int bin_of(float px, float py) {
    int bx = (int)floorf((px - X0) * (1.0f/HX));
    int by = (int)floorf((py - Y0) * (1.0f/HY));
    bx = min(max(bx, 0), BINX-1);
    by = min(max(by, 0), BINY-1);
    return by * BINX + bx;
}

__global__ __launch_bounds__(512) void k_nn() {
    __shared__ float4 srt[NPTS];          // 32 KB, bin-sorted points
    __shared__ int s_cnt[NBIN];
    __shared__ int s_start[NBIN];
    __shared__ int s_buf[NBIN];
    __shared__ int s_cur[NBIN];

    int b   = blockIdx.y;
    int tid = threadIdx.x;
    const float4* src = &g_pack[b * NPTS];

    // ---- build bins ----
    if (tid < NBIN) s_cnt[tid] = 0;
    __syncthreads();
    for (int j = tid; j < NPTS; j += 512) {
        float4 p = src[j];
        atomicAdd(&s_cnt[bin_of(p.x, p.y)], 1);
    }
    __syncthreads();
    s_buf[tid] = s_cnt[tid];
    __syncthreads();
    for (int off = 1; off < NBIN; off <<= 1) {
        int xv = s_buf[tid];
        int yv = (tid >= off) ? s_buf[tid - off] : 0;
        __syncthreads();
        s_buf[tid] = xv + yv;
        __syncthreads();
    }
    s_start[tid] = s_buf[tid] - s_cnt[tid];
    s_cur[tid]   = s_buf[tid] - s_cnt[tid];
    __syncthreads();
    for (int j = tid; j < NPTS; j += 512) {
        float4 p = src[j];
        int pos = atomicAdd(&s_cur[bin_of(p.x, p.y)], 1);
        srt[pos] = p;
    }
    __syncthreads();

    // ---- query (ilat fast so g_ft write is coalesced) ----
    int mI   = blockIdx.x * 512 + tid;
    int ilat = mI & (NLAT - 1);
    int jlon = mI >> 7;
    float gx = (float)ilat * (PI_F / (float)NLAT);
    float gy = (float)(jlon - NLAT) * (PI_F / (float)NLAT);
    float g2 = gx*gx + gy*gy;
    float gx2 = 2.0f * gx, gy2 = 2.0f * gy;
    float domY = fmaxf(gy, 0.0f);          // query dist to point domain y<=0
    float domY2 = domY * domY;

    int qbx = min(max((int)floorf((gx - X0) * (1.0f/HX)), 0), BINX-1);
    int qby = min(max((int)floorf((gy - Y0) * (1.0f/HY)), 0), BINY-1);

    float b0 = 3.4e38f, b1 = 3.4e38f, b2 = 3.4e38f;
    int   i0 = 0, i1 = 0, i2 = 0;

    #define SCAN_CELL(cx, cy) {                                             \
        int c = (cy) * BINX + (cx);                                         \
        int cnt = s_cnt[c];                                                 \
        if (cnt) {                                                          \
            float rx0 = X0 + (float)(cx) * HX;                              \
            float ry0 = Y0 + (float)(cy) * HY;                              \
            float ddx = fmaxf(fmaxf(rx0 - gx, gx - (rx0 + HX)), 0.0f);      \
            float ddy = fmaxf(fmaxf(ry0 - gy, gy - (ry0 + HY)), 0.0f);      \
            if (fmaf(ddx, ddx, ddy*ddy) < b2 + 1e-4f) {                     \
                int s = s_start[c], e = s + cnt;                            \
                for (int t = s; t < e; t++) {                               \
                    float4 sp = srt[t];                                     \
                    float cr = fmaf(gx2, sp.x, gy2 * sp.y);                 \
                    float d2 = (sp.z + g2) - cr;                            \
                    if (d2 < b2) {                                          \
                        if (d2 < b1) {                                      \
                            b2 = b1; i2 = i1;                               \
                            if (d2 < b0) { b1 = b0; i1 = i0; b0 = d2; i0 = t; } \
                            else         { b1 = d2; i1 = t; }               \
                        } else { b2 = d2; i2 = t; }                         \
                    }                                                       \
                }                                                           \
            }                                                               \
        }                                                                   \
    }

    for (int r = 0; r < BINX + 2; r++) {
        int xl = qbx - r, xr = qbx + r, yl = qby - r, yr = qby + r;
        int cxl = max(xl, 0), cxr = min(xr, BINX-1);
        if (r == 0) {
            SCAN_CELL(qbx, qby);
        } else {
            if (yl >= 0)      for (int x = cxl; x <= cxr; x++) SCAN_CELL(x, yl);
            if (yr <= BINY-1) for (int x = cxl; x <= cxr; x++) SCAN_CELL(x, yr);
            int cyl = max(yl + 1, 0), cyr = min(yr - 1, BINY-1);
            if (xl >= 0)      for (int y = cyl; y <= cyr; y++) SCAN_CELL(xl, y);
            if (xr <= BINX-1) for (int y = cyl; y <= cyr; y++) SCAN_CELL(xr, y);
        }
        bool fullX = (xl <= 0) && (xr >= BINX-1);
        bool fullY = (yl <= 0) && (yr >= BINY-1);
        if (fullX && fullY) break;
        // lower bounds on distance to unsearched cells.
        // x-slab cells also satisfy y in [-pi,0] -> add domY^2.
        float dbx = 3.4e38f, dby = 3.4e38f;
        if (xl > 0)        dbx = fminf(dbx, gx - (X0 + (float)xl * HX));
        if (xr < BINX-1)   dbx = fminf(dbx, (X0 + (float)(xr+1) * HX) - gx);
        if (yl > 0)        dby = fminf(dby, gy - (Y0 + (float)yl * HY));
        if (yr < BINY-1)   dby = fminf(dby, fmaxf(0.0f, (Y0 + (float)(yr+1) * HY) - gy));
        float dlb2 = fminf(fmaf(dbx, dbx, domY2), dby * dby);
        if (b2 < dlb2 - 1e-4f) break;
    }
    #undef SCAN_CELL

    float4 p0 = srt[i0], p1 = srt[i1], p2 = srt[i2];
    float dx, dy;
    dx = p0.x - gx; dy = p0.y - gy; float dd0 = sqrtf(dx*dx + dy*dy);
    dx = p1.x - gx; dy = p1.y - gy; float dd1 = sqrtf(dx*dx + dy*dy);
    dx = p2.x - gx; dy = p2.y - gy; float dd2 = sqrtf(dx*dx + dy*dy);
    float sum = dd0 + dd1 + dd2;
    float interp = (p0.w*dd0 + p1.w*dd1 + p2.w*dd2) / sum;

    g_ft[b][jlon][ilat] = interp;          // transposed, coalesced
}

// ---------------------------------------------------------------------------
// Kernel 3 (fused DFT + Legendre): block = (m, b), 128 threads.
// fp64 accumulators kill ordering-sensitivity of the cancellation-prone sums.
// ---------------------------------------------------------------------------
__global__ __launch_bounds__(128) void k_sht(float* __restrict__ out) {
    __shared__ float  ctab[NLON];
    __shared__ float  fre[NLAT];
    __shared__ float  sW[NLAT * LMAX];     // 25.6 KB
    __shared__ double ps[2][64];

    int m = blockIdx.x, b = blockIdx.y;
    int t = threadIdx.x;

    ctab[t]       = cospif((float)t * (1.0f / 128.0f));
    ctab[t + 128] = cospif((float)(t + 128) * (1.0f / 128.0f));
    const float* wsrc = &g_W[m][0][0];
    #pragma unroll
    for (int i = 0; i < NLAT * LMAX / 128; i++)
        sW[t + i * 128] = wsrc[t + i * 128];
    __syncthreads();

    // phase 1: DFT over longitude (double accumulation)
    const float* fp = &g_ft[b][0][t];      // stride NLAT between j's
    int m2 = (2 * m) & 255;
    double a0 = 0.0, a1 = 0.0;
    int idx = 0;
    #pragma unroll 4
    for (int j = 0; j < NLON; j += 2) {
        float f0 = fp[(j + 0) * NLAT];
        float f1 = fp[(j + 1) * NLAT];
        a0 = fma((double)f0, (double)ctab[idx], a0);
        a1 = fma((double)f1, (double)ctab[(idx + m) & 255], a1);
        idx = (idx + m2) & 255;
    }
    fre[t] = (float)((a0 + a1) * (2.0 * 3.14159265358979323846 / (double)NLON));
    __syncthreads();

    // phase 2: coeff[l] = sum_k fre[k] * W[k][l], split over 2 k-halves
    int g = t >> 6, l = t & 63;
    if (l < LMAX) {
        double p = 0.0;
        int k0 = g * 64;
        #pragma unroll 8
        for (int k = k0; k < k0 + 64; k++)
            p = fma((double)fre[k], (double)sW[k * LMAX + l], p);
        ps[g][l] = p;
    }
    __syncthreads();
    if (t < LMAX)
        out[(b * LMAX + t) * MMAX + m] = (float)(ps[0][t] + ps[1][t]);
}

// ---------------------------------------------------------------------------
extern "C" void kernel_launch(void* const* d_in, const int* in_sizes, int n_in,
                              void* d_out, int out_size) {
    const float* tgt = (const float*)d_in[0];
    float* out = (float*)d_out;

    k_init<<<16 + MMAX, 256>>>(tgt);
    k_nn<<<dim3(MGRID / 512, BATCH), 512>>>();
    k_sht<<<dim3(MMAX, BATCH), 128>>>(out);
}

// round 6
// speedup vs baseline: 1.9846x; 1.9846x over previous
#include <cuda_runtime.h>
#include <math.h>

#define NLAT  128
#define NLON  256
#define LMAX  50
#define MMAX  50
#define BATCH 2
#define NPTS  2048
#define MGRID (NLAT*NLON)
#define PI_F  3.14159265358979323846f

// bin grid over point domain [-pi,pi] x [-pi,0]
#define BINX 32
#define BINY 16
#define NBIN (BINX*BINY)
#define HX (2.0f*PI_F/(float)BINX)
#define HY (PI_F/(float)BINY)
#define X0 (-PI_F)
#define Y0 (-PI_F)

// Scratch (allocation-free rule: __device__ globals)
__device__ float4 g_pack[BATCH*NPTS];            // phi, theta-pi, s2, rho
__device__ float  g_W[MMAX][NLAT][LMAX];         // legendre*ccw, k-major
__device__ float  g_ft[BATCH][NLON][NLAT];       // interpolated grid, TRANSPOSED

__device__ __forceinline__ float f_rcp(float v)  { float r; asm("rcp.approx.f32 %0,%1;"  : "=f"(r) : "f"(v)); return r; }

// ---------------------------------------------------------------------------
// Kernel 1 (fused): blocks [0,16): cart->spherical; blocks [16,66): weights
// ---------------------------------------------------------------------------
__global__ void k_init(const float* __restrict__ tgt) {
    int blk = blockIdx.x;
    int t   = threadIdx.x;
    if (blk < 16) {
        int i = blk * 256 + t;
        float x = tgt[3*i + 0];
        float y = tgt[3*i + 1];
        float z = tgt[3*i + 2];
        float rho = sqrtf(x*x + y*y + z*z);
        float phi = atan2f(y, x);
        float th  = acosf(z / rho) - PI_F;
        float s2  = phi*phi + th*th;
        g_pack[i] = make_float4(phi, th, s2, rho);
        return;
    }
    if (t >= NLAT) return;           // weights part: 128 threads (k = t)

    __shared__ float sa[64];         // a(l)  for l = m+1+idx
    __shared__ float sbb[64];        // bb(l) for l = m+2+idx
    __shared__ float rp[64];         // prefactor product workspace

    int m = blk - 16;

    // --- k-independent coefficients, in parallel, precise sqrt ---
    if (t < 64) {
        int l = m + 1 + t;
        if (l < LMAX)
            sa[t] = sqrtf((float)(4*l*l - 1) / (float)(l*l - m*m));
        int l2 = m + 2 + t;
        if (l2 < LMAX) {
            int lm = l2 - 1;
            sbb[t] = sqrtf((float)(lm*lm - m*m) / (float)(4*lm*lm - 1));
        }
        rp[t] = (t >= 1 && t <= m) ? ((float)(2*t + 1) / (float)(2*t)) : 1.0f;
    }
    __syncthreads();
    // tree-product of rp[0..63]
    #pragma unroll
    for (int off = 32; off >= 1; off >>= 1) {
        if (t < off) rp[t] *= rp[t + off];
        __syncthreads();
    }
    float pref = sqrtf(rp[0] * (1.0f / (4.0f * PI_F)));   // sqrt(prod/(4pi))

    // --- per-k part ---
    int k = t;
    float tfrac = (float)k * (1.0f / 127.0f);
    float x = cospif(tfrac);
    float s = sinpif(tfrac);

    // Clenshaw-Curtis weight via Chebyshev recurrence
    float c1 = cospif(2.0f * tfrac);
    float cprev = 1.0f, ccur = c1;
    float S = 0.0f;
    #pragma unroll 7
    for (int kk = 1; kk <= 63; kk++) {
        float coef = 2.0f * f_rcp((float)(4*kk*kk - 1));
        S = fmaf(coef, ccur, S);
        float cnext = fmaf(2.0f * c1, ccur, -cprev);
        cprev = ccur; ccur = cnext;
    }
    float w = (2.0f / 127.0f) * (1.0f - S);
    if (k == 0 || k == NLAT - 1) w *= 0.5f;

    // (-s)^m via binary exponentiation
    float sm = 1.0f, base = -s;
    int e = m;
    while (e) { if (e & 1) sm *= base; base *= base; e >>= 1; }
    float pmm = pref * sm;

    for (int l = 0; l < m; l++) g_W[m][k][l] = 0.0f;
    g_W[m][k][m] = pmm * w;

    if (m + 1 < LMAX) {
        float p2 = pmm;
        float p1 = sa[0] * x * pmm;
        g_W[m][k][m+1] = p1 * w;
        for (int l = m + 2; l < LMAX; l++) {
            float p = sa[l - m - 1] * (x * p1 - sbb[l - m - 2] * p2);
            g_W[m][k][l] = p * w;
            p2 = p1; p1 = p;
        }
    }
}

// ---------------------------------------------------------------------------
// Kernel 2: binned 3-NN with per-cell rect pruning + domain-aware termination
// ---------------------------------------------------------------------------
__device__ __forceinline__ int bin_of(float px, float py) {
    int bx = (int)floorf((px - X0) * (1.0f/HX));
    int by = (int)floorf((py - Y0) * (1.0f/HY));
    bx = min(max(bx, 0), BINX-1);
    by = min(max(by, 0), BINY-1);
    return by * BINX + bx;
}

__global__ __launch_bounds__(512) void k_nn() {
    __shared__ float4 srt[NPTS];          // 32 KB, bin-sorted points
    __shared__ int s_cnt[NBIN];
    __shared__ int s_start[NBIN];
    __shared__ int s_buf[NBIN];
    __shared__ int s_cur[NBIN];

    int b   = blockIdx.y;
    int tid = threadIdx.x;
    const float4* src = &g_pack[b * NPTS];

    // ---- build bins ----
    if (tid < NBIN) s_cnt[tid] = 0;
    __syncthreads();
    for (int j = tid; j < NPTS; j += 512) {
        float4 p = src[j];
        atomicAdd(&s_cnt[bin_of(p.x, p.y)], 1);
    }
    __syncthreads();
    s_buf[tid] = s_cnt[tid];
    __syncthreads();
    for (int off = 1; off < NBIN; off <<= 1) {
        int xv = s_buf[tid];
        int yv = (tid >= off) ? s_buf[tid - off] : 0;
        __syncthreads();
        s_buf[tid] = xv + yv;
        __syncthreads();
    }
    s_start[tid] = s_buf[tid] - s_cnt[tid];
    s_cur[tid]   = s_buf[tid] - s_cnt[tid];
    __syncthreads();
    for (int j = tid; j < NPTS; j += 512) {
        float4 p = src[j];
        int pos = atomicAdd(&s_cur[bin_of(p.x, p.y)], 1);
        srt[pos] = p;
    }
    __syncthreads();

    // ---- query (ilat fast so g_ft write is coalesced) ----
    int mI   = blockIdx.x * 512 + tid;
    int ilat = mI & (NLAT - 1);
    int jlon = mI >> 7;
    // match reference grid rounding: (g / nlat) * pi
    float gx = __fmul_rn((float)ilat * (1.0f/128.0f), PI_F);
    float gy = __fmul_rn((float)(jlon - NLAT) * (1.0f/128.0f), PI_F);
    float g2 = gx*gx + gy*gy;
    float gx2 = 2.0f * gx, gy2 = 2.0f * gy;
    float domY = fmaxf(gy, 0.0f);
    float domY2 = domY * domY;

    int qbx = min(max((int)floorf((gx - X0) * (1.0f/HX)), 0), BINX-1);
    int qby = min(max((int)floorf((gy - Y0) * (1.0f/HY)), 0), BINY-1);

    float b0 = 3.4e38f, b1 = 3.4e38f, b2 = 3.4e38f;
    int   i0 = 0, i1 = 0, i2 = 0;

    #define SCAN_CELL(cx, cy) {                                             \
        int c = (cy) * BINX + (cx);                                         \
        int cnt = s_cnt[c];                                                 \
        if (cnt) {                                                          \
            float rx0 = X0 + (float)(cx) * HX;                              \
            float ry0 = Y0 + (float)(cy) * HY;                              \
            float ddx = fmaxf(fmaxf(rx0 - gx, gx - (rx0 + HX)), 0.0f);      \
            float ddy = fmaxf(fmaxf(ry0 - gy, gy - (ry0 + HY)), 0.0f);      \
            if (fmaf(ddx, ddx, ddy*ddy) < b2 + 1e-4f) {                     \
                int s = s_start[c], e = s + cnt;                            \
                for (int t = s; t < e; t++) {                               \
                    float4 sp = srt[t];                                     \
                    float cr = fmaf(gx2, sp.x, gy2 * sp.y);                 \
                    float d2 = (sp.z + g2) - cr;                            \
                    if (d2 < b2) {                                          \
                        if (d2 < b1) {                                      \
                            b2 = b1; i2 = i1;                               \
                            if (d2 < b0) { b1 = b0; i1 = i0; b0 = d2; i0 = t; } \
                            else         { b1 = d2; i1 = t; }               \
                        } else { b2 = d2; i2 = t; }                         \
                    }                                                       \
                }                                                           \
            }                                                               \
        }                                                                   \
    }

    for (int r = 0; r < BINX + 2; r++) {
        int xl = qbx - r, xr = qbx + r, yl = qby - r, yr = qby + r;
        int cxl = max(xl, 0), cxr = min(xr, BINX-1);
        if (r == 0) {
            SCAN_CELL(qbx, qby);
        } else {
            if (yl >= 0)      for (int x = cxl; x <= cxr; x++) SCAN_CELL(x, yl);
            if (yr <= BINY-1) for (int x = cxl; x <= cxr; x++) SCAN_CELL(x, yr);
            int cyl = max(yl + 1, 0), cyr = min(yr - 1, BINY-1);
            if (xl >= 0)      for (int y = cyl; y <= cyr; y++) SCAN_CELL(xl, y);
            if (xr <= BINX-1) for (int y = cyl; y <= cyr; y++) SCAN_CELL(xr, y);
        }
        bool fullX = (xl <= 0) && (xr >= BINX-1);
        bool fullY = (yl <= 0) && (yr >= BINY-1);
        if (fullX && fullY) break;
        float dbx = 3.4e38f, dby = 3.4e38f;
        if (xl > 0)        dbx = fminf(dbx, gx - (X0 + (float)xl * HX));
        if (xr < BINX-1)   dbx = fminf(dbx, (X0 + (float)(xr+1) * HX) - gx);
        if (yl > 0)        dby = fminf(dby, gy - (Y0 + (float)yl * HY));
        if (yr < BINY-1)   dby = fminf(dby, fmaxf(0.0f, (Y0 + (float)(yr+1) * HY) - gy));
        float dlb2 = fminf(fmaf(dbx, dbx, domY2), dby * dby);
        if (b2 < dlb2 - 1e-4f) break;
    }
    #undef SCAN_CELL

    // reference rounding: dist, w = dist/sum, interp = (r0w0 + r1w1) + r2w2
    float4 p0 = srt[i0], p1 = srt[i1], p2 = srt[i2];
    float dx, dy;
    dx = p0.x - gx; dy = p0.y - gy;
    float dd0 = sqrtf(__fadd_rn(__fmul_rn(dx,dx), __fmul_rn(dy,dy)));
    dx = p1.x - gx; dy = p1.y - gy;
    float dd1 = sqrtf(__fadd_rn(__fmul_rn(dx,dx), __fmul_rn(dy,dy)));
    dx = p2.x - gx; dy = p2.y - gy;
    float dd2 = sqrtf(__fadd_rn(__fmul_rn(dx,dx), __fmul_rn(dy,dy)));
    float sum = __fadd_rn(__fadd_rn(dd0, dd1), dd2);
    float w0 = __fdiv_rn(dd0, sum);
    float w1 = __fdiv_rn(dd1, sum);
    float w2 = __fdiv_rn(dd2, sum);
    float interp = __fadd_rn(__fadd_rn(__fmul_rn(p0.w, w0), __fmul_rn(p1.w, w1)),
                             __fmul_rn(p2.w, w2));

    g_ft[b][jlon][ilat] = interp;          // transposed, coalesced
}

// ---------------------------------------------------------------------------
// Kernel 3 (fused DFT + Legendre), fp32, 256 threads, split-j DFT.
// ---------------------------------------------------------------------------
__global__ __launch_bounds__(256) void k_sht(float* __restrict__ out) {
    __shared__ float ctab[NLON];
    __shared__ float sW[NLAT * LMAX];      // 25.6 KB
    __shared__ float pf[2][NLAT];
    __shared__ float fre[NLAT];
    __shared__ float ps[4][64];

    int m = blockIdx.x, b = blockIdx.y;
    int t = threadIdx.x;

    ctab[t] = cospif((float)t * (1.0f / 128.0f));
    const float* wsrc = &g_W[m][0][0];
    #pragma unroll
    for (int i = 0; i < NLAT * LMAX / 256; i++)
        sW[t + i * 256] = wsrc[t + i * 256];
    __syncthreads();

    // phase 1: DFT over longitude, two threads per k (j-halves)
    int k = t & 127, h = t >> 7;
    int j0 = h * 128;
    const float* fp = &g_ft[b][j0][k];
    int idx = (m * j0) & 255;
    int m2  = (2 * m) & 255;
    float a0 = 0.f, a1 = 0.f;
    #pragma unroll 8
    for (int jj = 0; jj < 128; jj += 2) {
        float f0 = fp[(jj + 0) * NLAT];
        float f1 = fp[(jj + 1) * NLAT];
        a0 = fmaf(f0, ctab[idx], a0);
        a1 = fmaf(f1, ctab[(idx + m) & 255], a1);
        idx = (idx + m2) & 255;
    }
    pf[h][k] = a0 + a1;
    __syncthreads();
    if (t < NLAT)
        fre[t] = (pf[0][t] + pf[1][t]) * (2.0f * PI_F / (float)NLON);
    __syncthreads();

    // phase 2: coeff[l] = sum_k fre[k] * W[k][l], 4-way split-K
    int g = t >> 6, l = t & 63;
    if (l < LMAX) {
        float p = 0.f;
        int k0 = g * 32;
        #pragma unroll 8
        for (int kk = k0; kk < k0 + 32; kk++)
            p = fmaf(fre[kk], sW[kk * LMAX + l], p);
        ps[g][l] = p;
    }
    __syncthreads();
    if (t < LMAX)
        out[(b * LMAX + t) * MMAX + m] = (ps[0][t] + ps[1][t]) + (ps[2][t] + ps[3][t]);
}

// ---------------------------------------------------------------------------
extern "C" void kernel_launch(void* const* d_in, const int* in_sizes, int n_in,
                              void* d_out, int out_size) {
    const float* tgt = (const float*)d_in[0];
    float* out = (float*)d_out;

    k_init<<<16 + MMAX, 256>>>(tgt);
    k_nn<<<dim3(MGRID / 512, BATCH), 512>>>();
    k_sht<<<dim3(MMAX, BATCH), 256>>>(out);
}

// round 7
// speedup vs baseline: 2.2435x; 1.1304x over previous
#include <cuda_runtime.h>
#include <math.h>

#define NLAT  128
#define NLON  256
#define LMAX  50
#define MMAX  50
#define BATCH 2
#define NPTS  2048
#define MGRID (NLAT*NLON)
#define PI_F  3.14159265358979323846f

// bin grid over point domain [-pi,pi] x [-pi,0]
#define BINX 32
#define BINY 16
#define NBIN (BINX*BINY)
#define HX (2.0f*PI_F/(float)BINX)
#define HY (PI_F/(float)BINY)
#define X0 (-PI_F)
#define Y0 (-PI_F)

// Scratch (allocation-free rule: __device__ globals)
__device__ float g_ft[BATCH][NLON][NLAT];        // interpolated grid, TRANSPOSED

__device__ __forceinline__ float f_rcp(float v)  { float r; asm("rcp.approx.f32 %0,%1;"  : "=f"(r) : "f"(v)); return r; }
__device__ __forceinline__ float f_div(float a, float b){ float r; asm("div.approx.f32 %0,%1,%2;" : "=f"(r) : "f"(a), "f"(b)); return r; }

// ---------------------------------------------------------------------------
// Kernel 1: cart->sph conversion + binned 3-NN + interpolation (fused)
// grid (64, BATCH), 512 threads
// ---------------------------------------------------------------------------
__device__ __forceinline__ int bin_of(float px, float py) {
    int bx = (int)floorf((px - X0) * (1.0f/HX));
    int by = (int)floorf((py - Y0) * (1.0f/HY));
    bx = min(max(bx, 0), BINX-1);
    by = min(max(by, 0), BINY-1);
    return by * BINX + bx;
}

__global__ __launch_bounds__(512) void k_nn(const float* __restrict__ tgt) {
    __shared__ float4 srt[NPTS];          // 32 KB, bin-sorted points
    __shared__ int s_cnt[NBIN];
    __shared__ int s_start[NBIN];
    __shared__ int s_buf[NBIN];
    __shared__ int s_cur[NBIN];

    int b   = blockIdx.y;
    int tid = threadIdx.x;

    // ---- convert this batch's points (4 per thread), keep in registers ----
    float4 pv[4];
    #pragma unroll
    for (int u = 0; u < 4; u++) {
        int j = tid + u * 512;
        const float* tp = &tgt[(b * NPTS + j) * 3];
        float x = tp[0], y = tp[1], z = tp[2];
        float rho = sqrtf(x*x + y*y + z*z);
        float phi = atan2f(y, x);
        float th  = acosf(z / rho) - PI_F;
        float s2  = phi*phi + th*th;
        pv[u] = make_float4(phi, th, s2, rho);
    }

    // ---- build bins ----
    if (tid < NBIN) s_cnt[tid] = 0;
    __syncthreads();
    #pragma unroll
    for (int u = 0; u < 4; u++)
        atomicAdd(&s_cnt[bin_of(pv[u].x, pv[u].y)], 1);
    __syncthreads();
    s_buf[tid] = s_cnt[tid];
    __syncthreads();
    for (int off = 1; off < NBIN; off <<= 1) {
        int xv = s_buf[tid];
        int yv = (tid >= off) ? s_buf[tid - off] : 0;
        __syncthreads();
        s_buf[tid] = xv + yv;
        __syncthreads();
    }
    s_start[tid] = s_buf[tid] - s_cnt[tid];
    s_cur[tid]   = s_buf[tid] - s_cnt[tid];
    __syncthreads();
    #pragma unroll
    for (int u = 0; u < 4; u++) {
        int pos = atomicAdd(&s_cur[bin_of(pv[u].x, pv[u].y)], 1);
        srt[pos] = pv[u];
    }
    __syncthreads();

    // ---- query (ilat fast so g_ft write is coalesced) ----
    int mI   = blockIdx.x * 512 + tid;
    int ilat = mI & (NLAT - 1);
    int jlon = mI >> 7;
    float gx = __fmul_rn((float)ilat * (1.0f/128.0f), PI_F);
    float gy = __fmul_rn((float)(jlon - NLAT) * (1.0f/128.0f), PI_F);
    float g2 = gx*gx + gy*gy;
    float gx2 = 2.0f * gx, gy2 = 2.0f * gy;
    float domY = fmaxf(gy, 0.0f);
    float domY2 = domY * domY;

    int qbx = min(max((int)floorf((gx - X0) * (1.0f/HX)), 0), BINX-1);
    int qby = min(max((int)floorf((gy - Y0) * (1.0f/HY)), 0), BINY-1);

    float b0 = 3.4e38f, b1 = 3.4e38f, b2 = 3.4e38f;
    int   i0 = 0, i1 = 0, i2 = 0;

    #define SCAN_CELL(cx, cy) {                                             \
        int c = (cy) * BINX + (cx);                                         \
        int cnt = s_cnt[c];                                                 \
        if (cnt) {                                                          \
            float rx0 = X0 + (float)(cx) * HX;                              \
            float ry0 = Y0 + (float)(cy) * HY;                              \
            float ddx = fmaxf(fmaxf(rx0 - gx, gx - (rx0 + HX)), 0.0f);      \
            float ddy = fmaxf(fmaxf(ry0 - gy, gy - (ry0 + HY)), 0.0f);      \
            if (fmaf(ddx, ddx, ddy*ddy) < b2 + 1e-4f) {                     \
                int s = s_start[c], e = s + cnt;                            \
                for (int t = s; t < e; t++) {                               \
                    float4 sp = srt[t];                                     \
                    float cr = fmaf(gx2, sp.x, gy2 * sp.y);                 \
                    float d2 = (sp.z + g2) - cr;                            \
                    if (d2 < b2) {                                          \
                        if (d2 < b1) {                                      \
                            b2 = b1; i2 = i1;                               \
                            if (d2 < b0) { b1 = b0; i1 = i0; b0 = d2; i0 = t; } \
                            else         { b1 = d2; i1 = t; }               \
                        } else { b2 = d2; i2 = t; }                         \
                    }                                                       \
                }                                                           \
            }                                                               \
        }                                                                   \
    }

    for (int r = 0; r < BINX + 2; r++) {
        int xl = qbx - r, xr = qbx + r, yl = qby - r, yr = qby + r;
        int cxl = max(xl, 0), cxr = min(xr, BINX-1);
        if (r == 0) {
            SCAN_CELL(qbx, qby);
        } else {
            if (yl >= 0)      for (int x = cxl; x <= cxr; x++) SCAN_CELL(x, yl);
            if (yr <= BINY-1) for (int x = cxl; x <= cxr; x++) SCAN_CELL(x, yr);
            int cyl = max(yl + 1, 0), cyr = min(yr - 1, BINY-1);
            if (xl >= 0)      for (int y = cyl; y <= cyr; y++) SCAN_CELL(xl, y);
            if (xr <= BINX-1) for (int y = cyl; y <= cyr; y++) SCAN_CELL(xr, y);
        }
        bool fullX = (xl <= 0) && (xr >= BINX-1);
        bool fullY = (yl <= 0) && (yr >= BINY-1);
        if (fullX && fullY) break;
        float dbx = 3.4e38f, dby = 3.4e38f;
        if (xl > 0)        dbx = fminf(dbx, gx - (X0 + (float)xl * HX));
        if (xr < BINX-1)   dbx = fminf(dbx, (X0 + (float)(xr+1) * HX) - gx);
        if (yl > 0)        dby = fminf(dby, gy - (Y0 + (float)yl * HY));
        if (yr < BINY-1)   dby = fminf(dby, fmaxf(0.0f, (Y0 + (float)(yr+1) * HY) - gy));
        float dlb2 = fminf(fmaf(dbx, dbx, domY2), dby * dby);
        if (b2 < dlb2 - 1e-4f) break;
    }
    #undef SCAN_CELL

    float4 p0 = srt[i0], p1 = srt[i1], p2 = srt[i2];
    float dx, dy;
    dx = p0.x - gx; dy = p0.y - gy;
    float dd0 = sqrtf(__fadd_rn(__fmul_rn(dx,dx), __fmul_rn(dy,dy)));
    dx = p1.x - gx; dy = p1.y - gy;
    float dd1 = sqrtf(__fadd_rn(__fmul_rn(dx,dx), __fmul_rn(dy,dy)));
    dx = p2.x - gx; dy = p2.y - gy;
    float dd2 = sqrtf(__fadd_rn(__fmul_rn(dx,dx), __fmul_rn(dy,dy)));
    float sum = __fadd_rn(__fadd_rn(dd0, dd1), dd2);
    float w0 = __fdiv_rn(dd0, sum);
    float w1 = __fdiv_rn(dd1, sum);
    float w2 = __fdiv_rn(dd2, sum);
    float interp = __fadd_rn(__fadd_rn(__fmul_rn(p0.w, w0), __fmul_rn(p1.w, w1)),
                             __fmul_rn(p2.w, w2));

    g_ft[b][jlon][ilat] = interp;          // transposed, coalesced
}

// ---------------------------------------------------------------------------
// Kernel 2 (fused weights + DFT + Legendre): block = (m, b), 256 threads.
// Warp-specialized: t<128 compute the Legendre*CC weight tile for this m
// (into smem) while t>=128 run the longitude DFT (global loads overlap).
// DFT summation order is bit-identical to the R6 kernel.
// ---------------------------------------------------------------------------
__global__ __launch_bounds__(256) void k_sht(float* __restrict__ out) {
    __shared__ float ctab[NLON];
    __shared__ float sW[NLAT * LMAX];      // 25.6 KB, k-major
    __shared__ float sa[64];
    __shared__ float sbb[64];
    __shared__ float fre[NLAT];
    __shared__ float ps[4][64];

    int m = blockIdx.x, b = blockIdx.y;
    int t = threadIdx.x;

    ctab[t] = cospif((float)t * (1.0f / 128.0f));
    if (t < 64) {
        int l = m + 1 + t;
        if (l < LMAX)
            sa[t] = sqrtf((float)(4*l*l - 1) / (float)(l*l - m*m));
        int l2 = m + 2 + t;
        if (l2 < LMAX) {
            int lm = l2 - 1;
            sbb[t] = sqrtf((float)(lm*lm - m*m) / (float)(4*lm*lm - 1));
        }
    }
    __syncthreads();

    if (t < 128) {
        // ---- weights for k = t ----
        int k = t;
        float tfrac = (float)k * (1.0f / 127.0f);
        float x = cospif(tfrac);
        float s = sinpif(tfrac);

        // Clenshaw-Curtis weight via Chebyshev recurrence
        float c1 = cospif(2.0f * tfrac);
        float cprev = 1.0f, ccur = c1;
        float S = 0.0f;
        #pragma unroll 7
        for (int kk = 1; kk <= 63; kk++) {
            float coef = 2.0f * f_rcp((float)(4*kk*kk - 1));
            S = fmaf(coef, ccur, S);
            float cnext = fmaf(2.0f * c1, ccur, -cprev);
            cprev = ccur; ccur = cnext;
        }
        float w = (2.0f / 127.0f) * (1.0f - S);
        if (k == 0 || k == NLAT - 1) w *= 0.5f;

        // prefactor sqrt( prod (2j+1)/(2j) / (4pi) )
        float pr = 1.0f;
        for (int mm = 1; mm <= m; mm++)
            pr *= f_div((float)(2*mm + 1), (float)(2*mm));
        float pref = sqrtf(pr * (1.0f / (4.0f * PI_F)));

        // (-s)^m via binary exponentiation
        float sm = 1.0f, base = -s;
        int e = m;
        while (e) { if (e & 1) sm *= base; base *= base; e >>= 1; }
        float pmm = pref * sm;

        float* wrow = &sW[k * LMAX];
        for (int l = 0; l < m; l++) wrow[l] = 0.0f;
        wrow[m] = pmm * w;
        if (m + 1 < LMAX) {
            float p2 = pmm;
            float p1 = sa[0] * x * pmm;
            wrow[m+1] = p1 * w;
            for (int l = m + 2; l < LMAX; l++) {
                float p = sa[l - m - 1] * (x * p1 - sbb[l - m - 2] * p2);
                wrow[l] = p * w;
                p2 = p1; p1 = p;
            }
        }
    } else {
        // ---- DFT for k = t-128 (summation order identical to R6) ----
        int k = t - 128;
        int m2 = (2 * m) & 255;
        const float* fp0 = &g_ft[b][0][k];
        float h[2];
        #pragma unroll
        for (int half = 0; half < 2; half++) {
            const float* fp = fp0 + (half * 128) * NLAT;
            int idx = (m * (half * 128)) & 255;
            float a0 = 0.f, a1 = 0.f;
            #pragma unroll 8
            for (int jj = 0; jj < 128; jj += 2) {
                float f0 = fp[(jj + 0) * NLAT];
                float f1 = fp[(jj + 1) * NLAT];
                a0 = fmaf(f0, ctab[idx], a0);
                a1 = fmaf(f1, ctab[(idx + m) & 255], a1);
                idx = (idx + m2) & 255;
            }
            h[half] = a0 + a1;
        }
        fre[k] = (h[0] + h[1]) * (2.0f * PI_F / (float)NLON);
    }
    __syncthreads();

    // ---- Legendre: coeff[l] = sum_k fre[k] * W[k][l], 4-way split-K ----
    int g = t >> 6, l = t & 63;
    if (l < LMAX) {
        float p = 0.f;
        int k0 = g * 32;
        #pragma unroll 8
        for (int kk = k0; kk < k0 + 32; kk++)
            p = fmaf(fre[kk], sW[kk * LMAX + l], p);
        ps[g][l] = p;
    }
    __syncthreads();
    if (t < LMAX)
        out[(b * LMAX + t) * MMAX + m] = (ps[0][t] + ps[1][t]) + (ps[2][t] + ps[3][t]);
}

// ---------------------------------------------------------------------------
extern "C" void kernel_launch(void* const* d_in, const int* in_sizes, int n_in,
                              void* d_out, int out_size) {
    const float* tgt = (const float*)d_in[0];
    float* out = (float*)d_out;

    k_nn<<<dim3(MGRID / 512, BATCH), 512>>>(tgt);
    k_sht<<<dim3(MMAX, BATCH), 256>>>(out);
}

// round 8
// speedup vs baseline: 2.4112x; 1.0748x over previous
#include <cuda_runtime.h>
#include <math.h>

#define NLAT  128
#define NLON  256
#define LMAX  50
#define MMAX  50
#define BATCH 2
#define NPTS  2048
#define MGRID (NLAT*NLON)
#define PI_F  3.14159265358979323846f

// bin grid over point domain [-pi,pi] x [-pi,0]
#define BINX 32
#define BINY 16
#define NBIN (BINX*BINY)
#define HX (2.0f*PI_F/(float)BINX)
#define HY (PI_F/(float)BINY)
#define X0 (-PI_F)
#define Y0 (-PI_F)

#define NN_BLOCKS  128           // 64 x BATCH
#define SHT_BLOCKS (MMAX*BATCH)  // 100
#define ALL_BLOCKS (NN_BLOCKS + SHT_BLOCKS)

// Scratch (allocation-free rule: __device__ globals)
__device__ float g_ft[BATCH][NLON][NLAT];   // interpolated grid, TRANSPOSED
__device__ int   g_arrive = 0;              // NN blocks done
__device__ int   g_done   = 0;              // SHT blocks done (for reset)

__device__ __forceinline__ float f_rcp(float v)  { float r; asm("rcp.approx.f32 %0,%1;"  : "=f"(r) : "f"(v)); return r; }
__device__ __forceinline__ float f_div(float a, float b){ float r; asm("div.approx.f32 %0,%1,%2;" : "=f"(r) : "f"(a), "f"(b)); return r; }

struct SmemNN {
    float4 srt[NPTS];            // 32 KB, bin-sorted points
    int cnt[NBIN];
    int start[NBIN];
    int buf[NBIN];
    int cur[NBIN];
};
struct SmemSHT {
    float ctab[NLON];
    float sW[NLAT * LMAX];       // 25.6 KB, k-major
    float sa[64];
    float sbb[64];
    float fre[NLAT];
    float pf[2][NLAT];
    float ps[4][64];
};

__device__ __forceinline__ int bin_of(float px, float py) {
    int bx = (int)floorf((px - X0) * (1.0f/HX));
    int by = (int)floorf((py - Y0) * (1.0f/HY));
    bx = min(max(bx, 0), BINX-1);
    by = min(max(by, 0), BINY-1);
    return by * BINX + bx;
}

// ---------------------------------------------------------------------------
// NN role: convert + bin + 3-NN + interpolate (identical math to R7)
// ---------------------------------------------------------------------------
__device__ void nn_role(const float* __restrict__ tgt, SmemNN* sm,
                        int nbid, int tid) {
    int b = nbid >> 6;                 // 64 blocks per batch
    int xb = nbid & 63;

    float4 pv[4];
    #pragma unroll
    for (int u = 0; u < 4; u++) {
        int j = tid + u * 512;
        const float* tp = &tgt[(b * NPTS + j) * 3];
        float x = tp[0], y = tp[1], z = tp[2];
        float rho = sqrtf(x*x + y*y + z*z);
        float phi = atan2f(y, x);
        float th  = acosf(z / rho) - PI_F;
        float s2  = phi*phi + th*th;
        pv[u] = make_float4(phi, th, s2, rho);
    }

    if (tid < NBIN) sm->cnt[tid] = 0;
    __syncthreads();
    #pragma unroll
    for (int u = 0; u < 4; u++)
        atomicAdd(&sm->cnt[bin_of(pv[u].x, pv[u].y)], 1);
    __syncthreads();
    sm->buf[tid] = sm->cnt[tid];
    __syncthreads();
    for (int off = 1; off < NBIN; off <<= 1) {
        int xv = sm->buf[tid];
        int yv = (tid >= off) ? sm->buf[tid - off] : 0;
        __syncthreads();
        sm->buf[tid] = xv + yv;
        __syncthreads();
    }
    sm->start[tid] = sm->buf[tid] - sm->cnt[tid];
    sm->cur[tid]   = sm->buf[tid] - sm->cnt[tid];
    __syncthreads();
    #pragma unroll
    for (int u = 0; u < 4; u++) {
        int pos = atomicAdd(&sm->cur[bin_of(pv[u].x, pv[u].y)], 1);
        sm->srt[pos] = pv[u];
    }
    __syncthreads();

    int mI   = xb * 512 + tid;
    int ilat = mI & (NLAT - 1);
    int jlon = mI >> 7;
    float gx = __fmul_rn((float)ilat * (1.0f/128.0f), PI_F);
    float gy = __fmul_rn((float)(jlon - NLAT) * (1.0f/128.0f), PI_F);
    float g2 = gx*gx + gy*gy;
    float gx2 = 2.0f * gx, gy2 = 2.0f * gy;
    float domY = fmaxf(gy, 0.0f);
    float domY2 = domY * domY;

    int qbx = min(max((int)floorf((gx - X0) * (1.0f/HX)), 0), BINX-1);
    int qby = min(max((int)floorf((gy - Y0) * (1.0f/HY)), 0), BINY-1);

    float b0 = 3.4e38f, b1 = 3.4e38f, b2 = 3.4e38f;
    int   i0 = 0, i1 = 0, i2 = 0;

    #define SCAN_CELL(cx, cy) {                                             \
        int c = (cy) * BINX + (cx);                                         \
        int cnt = sm->cnt[c];                                               \
        if (cnt) {                                                          \
            float rx0 = X0 + (float)(cx) * HX;                              \
            float ry0 = Y0 + (float)(cy) * HY;                              \
            float ddx = fmaxf(fmaxf(rx0 - gx, gx - (rx0 + HX)), 0.0f);      \
            float ddy = fmaxf(fmaxf(ry0 - gy, gy - (ry0 + HY)), 0.0f);      \
            if (fmaf(ddx, ddx, ddy*ddy) < b2 + 1e-4f) {                     \
                int s = sm->start[c], e = s + cnt;                          \
                for (int t = s; t < e; t++) {                               \
                    float4 sp = sm->srt[t];                                 \
                    float cr = fmaf(gx2, sp.x, gy2 * sp.y);                 \
                    float d2 = (sp.z + g2) - cr;                            \
                    if (d2 < b2) {                                          \
                        if (d2 < b1) {                                      \
                            b2 = b1; i2 = i1;                               \
                            if (d2 < b0) { b1 = b0; i1 = i0; b0 = d2; i0 = t; } \
                            else         { b1 = d2; i1 = t; }               \
                        } else { b2 = d2; i2 = t; }                         \
                    }                                                       \
                }                                                           \
            }                                                               \
        }                                                                   \
    }

    for (int r = 0; r < BINX + 2; r++) {
        int xl = qbx - r, xr = qbx + r, yl = qby - r, yr = qby + r;
        int cxl = max(xl, 0), cxr = min(xr, BINX-1);
        if (r == 0) {
            SCAN_CELL(qbx, qby);
        } else {
            if (yl >= 0)      for (int x = cxl; x <= cxr; x++) SCAN_CELL(x, yl);
            if (yr <= BINY-1) for (int x = cxl; x <= cxr; x++) SCAN_CELL(x, yr);
            int cyl = max(yl + 1, 0), cyr = min(yr - 1, BINY-1);
            if (xl >= 0)      for (int y = cyl; y <= cyr; y++) SCAN_CELL(xl, y);
            if (xr <= BINX-1) for (int y = cyl; y <= cyr; y++) SCAN_CELL(xr, y);
        }
        bool fullX = (xl <= 0) && (xr >= BINX-1);
        bool fullY = (yl <= 0) && (yr >= BINY-1);
        if (fullX && fullY) break;
        float dbx = 3.4e38f, dby = 3.4e38f;
        if (xl > 0)        dbx = fminf(dbx, gx - (X0 + (float)xl * HX));
        if (xr < BINX-1)   dbx = fminf(dbx, (X0 + (float)(xr+1) * HX) - gx);
        if (yl > 0)        dby = fminf(dby, gy - (Y0 + (float)yl * HY));
        if (yr < BINY-1)   dby = fminf(dby, fmaxf(0.0f, (Y0 + (float)(yr+1) * HY) - gy));
        float dlb2 = fminf(fmaf(dbx, dbx, domY2), dby * dby);
        if (b2 < dlb2 - 1e-4f) break;
    }
    #undef SCAN_CELL

    float4 p0 = sm->srt[i0], p1 = sm->srt[i1], p2 = sm->srt[i2];
    float dx, dy;
    dx = p0.x - gx; dy = p0.y - gy;
    float dd0 = sqrtf(__fadd_rn(__fmul_rn(dx,dx), __fmul_rn(dy,dy)));
    dx = p1.x - gx; dy = p1.y - gy;
    float dd1 = sqrtf(__fadd_rn(__fmul_rn(dx,dx), __fmul_rn(dy,dy)));
    dx = p2.x - gx; dy = p2.y - gy;
    float dd2 = sqrtf(__fadd_rn(__fmul_rn(dx,dx), __fmul_rn(dy,dy)));
    float sum = __fadd_rn(__fadd_rn(dd0, dd1), dd2);
    float w0 = __fdiv_rn(dd0, sum);
    float w1 = __fdiv_rn(dd1, sum);
    float w2 = __fdiv_rn(dd2, sum);
    float interp = __fadd_rn(__fadd_rn(__fmul_rn(p0.w, w0), __fmul_rn(p1.w, w1)),
                             __fmul_rn(p2.w, w2));

    g_ft[b][jlon][ilat] = interp;

    // release: grid data visible, then signal
    __syncthreads();
    __threadfence();
    if (tid == 0) atomicAdd(&g_arrive, 1);
}

// ---------------------------------------------------------------------------
// SHT role: weights (overlapped with NN via spin) + DFT + Legendre.
// DFT/Legendre summation trees bit-identical to R6/R7.
// ---------------------------------------------------------------------------
__device__ void sht_role(float* __restrict__ out, SmemSHT* sm,
                         int sbid, int tid) {
    int m = sbid % MMAX;
    int b = sbid / MMAX;
    int t = tid;

    if (t < NLON) sm->ctab[t] = cospif((float)t * (1.0f / 128.0f));
    if (t < 64) {
        int l = m + 1 + t;
        if (l < LMAX)
            sm->sa[t] = sqrtf((float)(4*l*l - 1) / (float)(l*l - m*m));
        int l2 = m + 2 + t;
        if (l2 < LMAX) {
            int lm = l2 - 1;
            sm->sbb[t] = sqrtf((float)(lm*lm - m*m) / (float)(4*lm*lm - 1));
        }
    }
    __syncthreads();

    // weights for k = t (t < 128), overlapped with the spin on t == 511
    if (t < 128) {
        int k = t;
        float tfrac = (float)k * (1.0f / 127.0f);
        float x = cospif(tfrac);
        float s = sinpif(tfrac);

        float c1 = cospif(2.0f * tfrac);
        float cprev = 1.0f, ccur = c1;
        float S = 0.0f;
        #pragma unroll 7
        for (int kk = 1; kk <= 63; kk++) {
            float coef = 2.0f * f_rcp((float)(4*kk*kk - 1));
            S = fmaf(coef, ccur, S);
            float cnext = fmaf(2.0f * c1, ccur, -cprev);
            cprev = ccur; ccur = cnext;
        }
        float w = (2.0f / 127.0f) * (1.0f - S);
        if (k == 0 || k == NLAT - 1) w *= 0.5f;

        float pr = 1.0f;
        for (int mm = 1; mm <= m; mm++)
            pr *= f_div((float)(2*mm + 1), (float)(2*mm));
        float pref = sqrtf(pr * (1.0f / (4.0f * PI_F)));

        float sgn = 1.0f, base = -s;
        int e = m;
        while (e) { if (e & 1) sgn *= base; base *= base; e >>= 1; }
        float pmm = pref * sgn;

        float* wrow = &sm->sW[k * LMAX];
        for (int l = 0; l < m; l++) wrow[l] = 0.0f;
        wrow[m] = pmm * w;
        if (m + 1 < LMAX) {
            float p2 = pmm;
            float p1 = sm->sa[0] * x * pmm;
            wrow[m+1] = p1 * w;
            for (int l = m + 2; l < LMAX; l++) {
                float p = sm->sa[l - m - 1] * (x * p1 - sm->sbb[l - m - 2] * p2);
                wrow[l] = p * w;
                p2 = p1; p1 = p;
            }
        }
    } else if (t == 511) {
        // acquire: wait for all NN blocks
        while (atomicAdd(&g_arrive, 0) < NN_BLOCKS) __nanosleep(128);
        __threadfence();
    }
    __syncthreads();

    // DFT: 2 threads per k (t in [128, 384)), bit-identical to R6 halves
    if (t >= 128 && t < 384) {
        int th = t - 128;
        int k = th & 127, half = th >> 7;
        int m2 = (2 * m) & 255;
        const float* fp = &g_ft[b][half * 128][k];
        int idx = (m * (half * 128)) & 255;
        float a0 = 0.f, a1 = 0.f;
        #pragma unroll 8
        for (int jj = 0; jj < 128; jj += 2) {
            float f0 = fp[(jj + 0) * NLAT];
            float f1 = fp[(jj + 1) * NLAT];
            a0 = fmaf(f0, sm->ctab[idx], a0);
            a1 = fmaf(f1, sm->ctab[(idx + m) & 255], a1);
            idx = (idx + m2) & 255;
        }
        sm->pf[half][k] = a0 + a1;
    }
    __syncthreads();
    if (t < NLAT)
        sm->fre[t] = (sm->pf[0][t] + sm->pf[1][t]) * (2.0f * PI_F / (float)NLON);
    __syncthreads();

    // Legendre: 4-way split-K (t < 256), identical tree to R7
    int g = t >> 6, l = t & 63;
    if (t < 256 && l < LMAX) {
        float p = 0.f;
        int k0 = g * 32;
        #pragma unroll 8
        for (int kk = k0; kk < k0 + 32; kk++)
            p = fmaf(sm->fre[kk], sm->sW[kk * LMAX + l], p);
        sm->ps[g][l] = p;
    }
    __syncthreads();
    if (t < LMAX)
        out[(b * LMAX + t) * MMAX + m] =
            (sm->ps[0][t] + sm->ps[1][t]) + (sm->ps[2][t] + sm->ps[3][t]);

    // reset flags for next (deterministic) run — last SHT block does it
    __syncthreads();
    if (t == 0) {
        __threadfence();
        int d = atomicAdd(&g_done, 1);
        if (d == SHT_BLOCKS - 1) {
            g_arrive = 0;
            g_done = 0;
            __threadfence();
        }
    }
}

// ---------------------------------------------------------------------------
__global__ __launch_bounds__(512, 2) void k_all(const float* __restrict__ tgt,
                                                float* __restrict__ out) {
    __shared__ union { SmemNN nn; SmemSHT sht; } smem;
    int bid = blockIdx.x;
    int tid = threadIdx.x;
    if (bid < NN_BLOCKS) nn_role(tgt, &smem.nn, bid, tid);
    else                 sht_role(out, &smem.sht, bid - NN_BLOCKS, tid);
}

// ---------------------------------------------------------------------------
extern "C" void kernel_launch(void* const* d_in, const int* in_sizes, int n_in,
                              void* d_out, int out_size) {
    const float* tgt = (const float*)d_in[0];
    float* out = (float*)d_out;
    k_all<<<ALL_BLOCKS, 512>>>(tgt, out);
}

// round 9
// speedup vs baseline: 2.6094x; 1.0822x over previous
#include <cuda_runtime.h>
#include <math.h>

#define NLAT  128
#define NLON  256
#define LMAX  50
#define MMAX  50
#define BATCH 2
#define NPTS  2048
#define MGRID (NLAT*NLON)
#define PI_F  3.14159265358979323846f

#define BINX 32
#define BINY 16
#define NBIN (BINX*BINY)
#define HX (2.0f*PI_F/(float)BINX)
#define HY (PI_F/(float)BINY)
#define X0 (-PI_F)
#define Y0 (-PI_F)

#define NN_BLOCKS  128           // 64 x BATCH
#define SHT_BLOCKS (MMAX*BATCH)  // 100
#define ALL_BLOCKS (NN_BLOCKS + SHT_BLOCKS)

__device__ float g_ft[BATCH][NLON][NLAT];   // interpolated grid, TRANSPOSED
__device__ int   g_arrive = 0;
__device__ int   g_done   = 0;

__device__ __forceinline__ float f_rcp(float v)  { float r; asm("rcp.approx.f32 %0,%1;"  : "=f"(r) : "f"(v)); return r; }
__device__ __forceinline__ float f_div(float a, float b){ float r; asm("div.approx.f32 %0,%1,%2;" : "=f"(r) : "f"(a), "f"(b)); return r; }

struct SmemNN {
    float4 srt[NPTS];            // 32 KB
    int cnt[NBIN];
    int start[NBIN];
    int cur[NBIN];
    int wsum[16];
};
struct SmemSHT {
    float ctab[NLON];
    float sW[NLAT * LMAX];       // 25.6 KB
    float sa[64];
    float sbb[64];
    float fre[NLAT];
    float pf[2][NLAT];
    float ps[4][64];
};

__device__ __forceinline__ int bin_of(float px, float py) {
    int bx = (int)floorf((px - X0) * (1.0f/HX));
    int by = (int)floorf((py - Y0) * (1.0f/HY));
    bx = min(max(bx, 0), BINX-1);
    by = min(max(by, 0), BINY-1);
    return by * BINX + bx;
}

// ---------------------------------------------------------------------------
// NN role
// ---------------------------------------------------------------------------
__device__ void nn_role(const float* __restrict__ tgt, SmemNN* sm,
                        int nbid, int tid) {
    int b = nbid >> 6;
    int xb = nbid & 63;

    float4 pv[4];
    #pragma unroll
    for (int u = 0; u < 4; u++) {
        int j = tid + u * 512;
        const float* tp = &tgt[(b * NPTS + j) * 3];
        float x = tp[0], y = tp[1], z = tp[2];
        float rho = sqrtf(x*x + y*y + z*z);
        float phi = atan2f(y, x);
        float th  = acosf(z / rho) - PI_F;
        float s2  = phi*phi + th*th;
        pv[u] = make_float4(phi, th, s2, rho);
    }

    if (tid < NBIN) sm->cnt[tid] = 0;
    __syncthreads();
    #pragma unroll
    for (int u = 0; u < 4; u++)
        atomicAdd(&sm->cnt[bin_of(pv[u].x, pv[u].y)], 1);
    __syncthreads();

    // --- warp-shfl scan over 512 bins (3 barriers total) ---
    int lane = tid & 31, wrp = tid >> 5;
    int v = sm->cnt[tid];
    int x = v;
    #pragma unroll
    for (int off = 1; off < 32; off <<= 1) {
        int y = __shfl_up_sync(0xFFFFFFFFu, x, off);
        if (lane >= off) x += y;
    }
    if (lane == 31) sm->wsum[wrp] = x;
    __syncthreads();
    if (wrp == 0) {
        int w = (lane < 16) ? sm->wsum[lane] : 0;
        #pragma unroll
        for (int off = 1; off < 16; off <<= 1) {
            int y = __shfl_up_sync(0xFFFFFFFFu, w, off);
            if (lane >= off) w += y;
        }
        if (lane < 16) sm->wsum[lane] = w;
    }
    __syncthreads();
    int incl = x + (wrp > 0 ? sm->wsum[wrp - 1] : 0);
    sm->start[tid] = incl - v;
    sm->cur[tid]   = incl - v;
    __syncthreads();

    #pragma unroll
    for (int u = 0; u < 4; u++) {
        int pos = atomicAdd(&sm->cur[bin_of(pv[u].x, pv[u].y)], 1);
        sm->srt[pos] = pv[u];
    }
    __syncthreads();

    int mI   = xb * 512 + tid;
    int ilat = mI & (NLAT - 1);
    int jlon = mI >> 7;
    float gx = __fmul_rn((float)ilat * (1.0f/128.0f), PI_F);
    float gy = __fmul_rn((float)(jlon - NLAT) * (1.0f/128.0f), PI_F);
    float g2 = gx*gx + gy*gy;
    float gx2 = 2.0f * gx, gy2 = 2.0f * gy;
    float domY = fmaxf(gy, 0.0f);
    float domY2 = domY * domY;

    int qbx = min(max((int)floorf((gx - X0) * (1.0f/HX)), 0), BINX-1);
    int qby = min(max((int)floorf((gy - Y0) * (1.0f/HY)), 0), BINY-1);

    float b0 = 3.4e38f, b1 = 3.4e38f, b2 = 3.4e38f;
    int   i0 = 0, i1 = 0, i2 = 0;

    #define SCAN_CELL(cx, cy) {                                             \
        int c = (cy) * BINX + (cx);                                         \
        int cnt = sm->cnt[c];                                               \
        if (cnt) {                                                          \
            float rx0 = X0 + (float)(cx) * HX;                              \
            float ry0 = Y0 + (float)(cy) * HY;                              \
            float ddx = fmaxf(fmaxf(rx0 - gx, gx - (rx0 + HX)), 0.0f);      \
            float ddy = fmaxf(fmaxf(ry0 - gy, gy - (ry0 + HY)), 0.0f);      \
            if (fmaf(ddx, ddx, ddy*ddy) < b2 + 1e-4f) {                     \
                int s = sm->start[c], e = s + cnt;                          \
                for (int t = s; t < e; t++) {                               \
                    float4 sp = sm->srt[t];                                 \
                    float cr = fmaf(gx2, sp.x, gy2 * sp.y);                 \
                    float d2 = (sp.z + g2) - cr;                            \
                    if (d2 < b2) {                                          \
                        if (d2 < b1) {                                      \
                            b2 = b1; i2 = i1;                               \
                            if (d2 < b0) { b1 = b0; i1 = i0; b0 = d2; i0 = t; } \
                            else         { b1 = d2; i1 = t; }               \
                        } else { b2 = d2; i2 = t; }                         \
                    }                                                       \
                }                                                           \
            }                                                               \
        }                                                                   \
    }

    for (int r = 0; r < BINX + 2; r++) {
        int xl = qbx - r, xr = qbx + r, yl = qby - r, yr = qby + r;
        int cxl = max(xl, 0), cxr = min(xr, BINX-1);
        if (r == 0) {
            SCAN_CELL(qbx, qby);
        } else {
            if (yl >= 0)      for (int x2 = cxl; x2 <= cxr; x2++) SCAN_CELL(x2, yl);
            if (yr <= BINY-1) for (int x2 = cxl; x2 <= cxr; x2++) SCAN_CELL(x2, yr);
            int cyl = max(yl + 1, 0), cyr = min(yr - 1, BINY-1);
            if (xl >= 0)      for (int y2 = cyl; y2 <= cyr; y2++) SCAN_CELL(xl, y2);
            if (xr <= BINX-1) for (int y2 = cyl; y2 <= cyr; y2++) SCAN_CELL(xr, y2);
        }
        bool fullX = (xl <= 0) && (xr >= BINX-1);
        bool fullY = (yl <= 0) && (yr >= BINY-1);
        if (fullX && fullY) break;
        float dbx = 3.4e38f, dby = 3.4e38f;
        if (xl > 0)        dbx = fminf(dbx, gx - (X0 + (float)xl * HX));
        if (xr < BINX-1)   dbx = fminf(dbx, (X0 + (float)(xr+1) * HX) - gx);
        if (yl > 0)        dby = fminf(dby, gy - (Y0 + (float)yl * HY));
        if (yr < BINY-1)   dby = fminf(dby, fmaxf(0.0f, (Y0 + (float)(yr+1) * HY) - gy));
        float dlb2 = fminf(fmaf(dbx, dbx, domY2), dby * dby);
        if (b2 < dlb2 - 1e-4f) break;
    }
    #undef SCAN_CELL

    float4 p0 = sm->srt[i0], p1 = sm->srt[i1], p2 = sm->srt[i2];
    float dx, dy;
    dx = p0.x - gx; dy = p0.y - gy;
    float dd0 = sqrtf(__fadd_rn(__fmul_rn(dx,dx), __fmul_rn(dy,dy)));
    dx = p1.x - gx; dy = p1.y - gy;
    float dd1 = sqrtf(__fadd_rn(__fmul_rn(dx,dx), __fmul_rn(dy,dy)));
    dx = p2.x - gx; dy = p2.y - gy;
    float dd2 = sqrtf(__fadd_rn(__fmul_rn(dx,dx), __fmul_rn(dy,dy)));
    float sum = __fadd_rn(__fadd_rn(dd0, dd1), dd2);
    float w0 = __fdiv_rn(dd0, sum);
    float w1 = __fdiv_rn(dd1, sum);
    float w2 = __fdiv_rn(dd2, sum);
    float interp = __fadd_rn(__fadd_rn(__fmul_rn(p0.w, w0), __fmul_rn(p1.w, w1)),
                             __fmul_rn(p2.w, w2));

    g_ft[b][jlon][ilat] = interp;

    __syncthreads();
    __threadfence();
    if (tid == 0) atomicAdd(&g_arrive, 1);
}

// ---------------------------------------------------------------------------
// SHT role: weights overlapped with NN; DFT with independent address calc
// (same FP summation tree as R6/R7/R8); Legendre 4-way split-K.
// ---------------------------------------------------------------------------
__device__ void sht_role(float* __restrict__ out, SmemSHT* sm,
                         int sbid, int tid) {
    int m = sbid % MMAX;
    int b = sbid / MMAX;
    int t = tid;

    if (t < NLON) sm->ctab[t] = cospif((float)t * (1.0f / 128.0f));
    if (t < 64) {
        int l = m + 1 + t;
        if (l < LMAX)
            sm->sa[t] = sqrtf((float)(4*l*l - 1) / (float)(l*l - m*m));
        int l2 = m + 2 + t;
        if (l2 < LMAX) {
            int lm = l2 - 1;
            sm->sbb[t] = sqrtf((float)(lm*lm - m*m) / (float)(4*lm*lm - 1));
        }
    }
    __syncthreads();

    if (t < 128) {
        int k = t;
        float tfrac = (float)k * (1.0f / 127.0f);
        float x = cospif(tfrac);
        float s = sinpif(tfrac);

        float c1 = cospif(2.0f * tfrac);
        float cprev = 1.0f, ccur = c1;
        float S = 0.0f;
        #pragma unroll 7
        for (int kk = 1; kk <= 63; kk++) {
            float coef = 2.0f * f_rcp((float)(4*kk*kk - 1));
            S = fmaf(coef, ccur, S);
            float cnext = fmaf(2.0f * c1, ccur, -cprev);
            cprev = ccur; ccur = cnext;
        }
        float w = (2.0f / 127.0f) * (1.0f - S);
        if (k == 0 || k == NLAT - 1) w *= 0.5f;

        float pr = 1.0f;
        for (int mm = 1; mm <= m; mm++)
            pr *= f_div((float)(2*mm + 1), (float)(2*mm));
        float pref = sqrtf(pr * (1.0f / (4.0f * PI_F)));

        float sgn = 1.0f, base = -s;
        int e = m;
        while (e) { if (e & 1) sgn *= base; base *= base; e >>= 1; }
        float pmm = pref * sgn;

        float* wrow = &sm->sW[k * LMAX];
        for (int l = 0; l < m; l++) wrow[l] = 0.0f;
        wrow[m] = pmm * w;
        if (m + 1 < LMAX) {
            float p2 = pmm;
            float p1 = sm->sa[0] * x * pmm;
            wrow[m+1] = p1 * w;
            for (int l = m + 2; l < LMAX; l++) {
                float p = sm->sa[l - m - 1] * (x * p1 - sm->sbb[l - m - 2] * p2);
                wrow[l] = p * w;
                p2 = p1; p1 = p;
            }
        }
    } else if (t == 511) {
        while (atomicAdd(&g_arrive, 0) < NN_BLOCKS) __nanosleep(128);
        __threadfence();
    }
    __syncthreads();

    // DFT: 2 threads per k; address math independent per iteration (MLP-bound)
    if (t >= 128 && t < 384) {
        int th = t - 128;
        int k = th & 127, half = th >> 7;
        const float* __restrict__ fp = &g_ft[b][half * 128][k];
        int base = (m * (half * 128)) & 255;
        float a0 = 0.f, a1 = 0.f;
        #pragma unroll 16
        for (int jj = 0; jj < 128; jj += 2) {
            float f0 = __ldg(&fp[(jj + 0) * NLAT]);
            float f1 = __ldg(&fp[(jj + 1) * NLAT]);
            int idx0 = (base + jj * m) & 255;
            int idx1 = (base + (jj + 1) * m) & 255;
            a0 = fmaf(f0, sm->ctab[idx0], a0);
            a1 = fmaf(f1, sm->ctab[idx1], a1);
        }
        sm->pf[half][k] = a0 + a1;
    }
    __syncthreads();
    if (t < NLAT)
        sm->fre[t] = (sm->pf[0][t] + sm->pf[1][t]) * (2.0f * PI_F / (float)NLON);
    __syncthreads();

    int g = t >> 6, l = t & 63;
    if (t < 256 && l < LMAX) {
        float p = 0.f;
        int k0 = g * 32;
        #pragma unroll 8
        for (int kk = k0; kk < k0 + 32; kk++)
            p = fmaf(sm->fre[kk], sm->sW[kk * LMAX + l], p);
        sm->ps[g][l] = p;
    }
    __syncthreads();
    if (t < LMAX)
        out[(b * LMAX + t) * MMAX + m] =
            (sm->ps[0][t] + sm->ps[1][t]) + (sm->ps[2][t] + sm->ps[3][t]);

    __syncthreads();
    if (t == 0) {
        __threadfence();
        int d = atomicAdd(&g_done, 1);
        if (d == SHT_BLOCKS - 1) {
            g_arrive = 0;
            g_done = 0;
            __threadfence();
        }
    }
}

// ---------------------------------------------------------------------------
__global__ __launch_bounds__(512, 2) void k_all(const float* __restrict__ tgt,
                                                float* __restrict__ out) {
    __shared__ union { SmemNN nn; SmemSHT sht; } smem;
    int bid = blockIdx.x;
    int tid = threadIdx.x;
    if (bid < NN_BLOCKS) nn_role(tgt, &smem.nn, bid, tid);
    else                 sht_role(out, &smem.sht, bid - NN_BLOCKS, tid);
}

// ---------------------------------------------------------------------------
extern "C" void kernel_launch(void* const* d_in, const int* in_sizes, int n_in,
                              void* d_out, int out_size) {
    const float* tgt = (const float*)d_in[0];
    float* out = (float*)d_out;
    k_all<<<ALL_BLOCKS, 512>>>(tgt, out);
}

// round 10
// speedup vs baseline: 2.8667x; 1.0986x over previous
#include <cuda_runtime.h>
#include <math.h>

#define NLAT  128
#define NLON  256
#define LMAX  50
#define MMAX  50
#define BATCH 2
#define NPTS  2048
#define MGRID (NLAT*NLON)
#define PI_F  3.14159265358979323846f

#define BINX 32
#define BINY 16
#define NBIN (BINX*BINY)
#define HX (2.0f*PI_F/(float)BINX)
#define HY (PI_F/(float)BINY)
#define X0 (-PI_F)
#define Y0 (-PI_F)

#define NN_BLOCKS  128           // 64 x BATCH
#define SHT_BLOCKS (MMAX*BATCH)  // 100
#define ALL_BLOCKS (NN_BLOCKS + SHT_BLOCKS)

__device__ float g_ft[BATCH][NLON][NLAT];   // interpolated grid, TRANSPOSED
__device__ int   g_arrive[BATCH] = {0, 0};
__device__ int   g_done = 0;

__device__ __forceinline__ float f_rcp(float v)  { float r; asm("rcp.approx.f32 %0,%1;"  : "=f"(r) : "f"(v)); return r; }
__device__ __forceinline__ float f_div(float a, float b){ float r; asm("div.approx.f32 %0,%1,%2;" : "=f"(r) : "f"(a), "f"(b)); return r; }

struct SmemNN {
    float4 srt[NPTS];            // 32 KB
    int cnt[NBIN];
    int start[NBIN];
    int cur[NBIN];
    int wsum[16];
};
struct SmemSHT {
    float ctab[NLON];
    float sW[NLAT * LMAX];       // 25.6 KB
    float sa[64];
    float sbb[64];
    float fre[NLAT];
    float pf[2][NLAT];
    float ps[4][64];
};

__device__ __forceinline__ int bin_of(float px, float py) {
    int bx = (int)floorf((px - X0) * (1.0f/HX));
    int by = (int)floorf((py - Y0) * (1.0f/HY));
    bx = min(max(bx, 0), BINX-1);
    by = min(max(by, 0), BINY-1);
    return by * BINX + bx;
}

// ---------------------------------------------------------------------------
// NN role
// ---------------------------------------------------------------------------
__device__ void nn_role(const float* __restrict__ tgt, SmemNN* sm,
                        int nbid, int tid) {
    int b = nbid >> 6;
    int xb = nbid & 63;

    float4 pv[4];
    #pragma unroll
    for (int u = 0; u < 4; u++) {
        int j = tid + u * 512;
        const float* tp = &tgt[(b * NPTS + j) * 3];
        float x = tp[0], y = tp[1], z = tp[2];
        float rho = sqrtf(x*x + y*y + z*z);
        float phi = atan2f(y, x);
        float th  = acosf(z / rho) - PI_F;
        float s2  = phi*phi + th*th;
        pv[u] = make_float4(phi, th, s2, rho);
    }

    if (tid < NBIN) sm->cnt[tid] = 0;
    __syncthreads();
    #pragma unroll
    for (int u = 0; u < 4; u++)
        atomicAdd(&sm->cnt[bin_of(pv[u].x, pv[u].y)], 1);
    __syncthreads();

    // warp-shfl scan over 512 bins
    int lane = tid & 31, wrp = tid >> 5;
    int v = sm->cnt[tid];
    int x = v;
    #pragma unroll
    for (int off = 1; off < 32; off <<= 1) {
        int y = __shfl_up_sync(0xFFFFFFFFu, x, off);
        if (lane >= off) x += y;
    }
    if (lane == 31) sm->wsum[wrp] = x;
    __syncthreads();
    if (wrp == 0) {
        int w = (lane < 16) ? sm->wsum[lane] : 0;
        #pragma unroll
        for (int off = 1; off < 16; off <<= 1) {
            int y = __shfl_up_sync(0xFFFFFFFFu, w, off);
            if (lane >= off) w += y;
        }
        if (lane < 16) sm->wsum[lane] = w;
    }
    __syncthreads();
    int incl = x + (wrp > 0 ? sm->wsum[wrp - 1] : 0);
    sm->start[tid] = incl - v;
    sm->cur[tid]   = incl - v;
    __syncthreads();

    #pragma unroll
    for (int u = 0; u < 4; u++) {
        int pos = atomicAdd(&sm->cur[bin_of(pv[u].x, pv[u].y)], 1);
        sm->srt[pos] = pv[u];
    }
    __syncthreads();

    // ---- query: warp-coherent 8x4 tiles ----
    // warp w covers ilat [8w, 8w+8) x jlon [4xb, 4xb+4)
    int ilat = wrp * 8 + (lane & 7);
    int jlon = xb * 4 + (lane >> 3);
    float gx = __fmul_rn((float)ilat * (1.0f/128.0f), PI_F);
    float gy = __fmul_rn((float)(jlon - NLAT) * (1.0f/128.0f), PI_F);
    float g2 = gx*gx + gy*gy;
    float gx2 = 2.0f * gx, gy2 = 2.0f * gy;
    float domY = fmaxf(gy, 0.0f);
    float domY2 = domY * domY;

    int qbx = min(max((int)floorf((gx - X0) * (1.0f/HX)), 0), BINX-1);
    int qby = min(max((int)floorf((gy - Y0) * (1.0f/HY)), 0), BINY-1);

    float b0 = 3.4e38f, b1 = 3.4e38f, b2 = 3.4e38f;
    int   i0 = 0, i1 = 0, i2 = 0;

    #define SCAN_CELL(cx, cy) {                                             \
        int c = (cy) * BINX + (cx);                                         \
        int cnt = sm->cnt[c];                                               \
        if (cnt) {                                                          \
            float rx0 = X0 + (float)(cx) * HX;                              \
            float ry0 = Y0 + (float)(cy) * HY;                              \
            float ddx = fmaxf(fmaxf(rx0 - gx, gx - (rx0 + HX)), 0.0f);      \
            float ddy = fmaxf(fmaxf(ry0 - gy, gy - (ry0 + HY)), 0.0f);      \
            if (fmaf(ddx, ddx, ddy*ddy) < b2 + 1e-4f) {                     \
                int s = sm->start[c], e = s + cnt;                          \
                for (int t = s; t < e; t++) {                               \
                    float4 sp = sm->srt[t];                                 \
                    float cr = fmaf(gx2, sp.x, gy2 * sp.y);                 \
                    float d2 = (sp.z + g2) - cr;                            \
                    if (d2 < b2) {                                          \
                        if (d2 < b1) {                                      \
                            b2 = b1; i2 = i1;                               \
                            if (d2 < b0) { b1 = b0; i1 = i0; b0 = d2; i0 = t; } \
                            else         { b1 = d2; i1 = t; }               \
                        } else { b2 = d2; i2 = t; }                         \
                    }                                                       \
                }                                                           \
            }                                                               \
        }                                                                   \
    }

    for (int r = 0; r < BINX + 2; r++) {
        int xl = qbx - r, xr = qbx + r, yl = qby - r, yr = qby + r;
        int cxl = max(xl, 0), cxr = min(xr, BINX-1);
        if (r == 0) {
            SCAN_CELL(qbx, qby);
        } else {
            if (yl >= 0)      for (int x2 = cxl; x2 <= cxr; x2++) SCAN_CELL(x2, yl);
            if (yr <= BINY-1) for (int x2 = cxl; x2 <= cxr; x2++) SCAN_CELL(x2, yr);
            int cyl = max(yl + 1, 0), cyr = min(yr - 1, BINY-1);
            if (xl >= 0)      for (int y2 = cyl; y2 <= cyr; y2++) SCAN_CELL(xl, y2);
            if (xr <= BINX-1) for (int y2 = cyl; y2 <= cyr; y2++) SCAN_CELL(xr, y2);
        }
        bool fullX = (xl <= 0) && (xr >= BINX-1);
        bool fullY = (yl <= 0) && (yr >= BINY-1);
        if (fullX && fullY) break;
        float dbx = 3.4e38f, dby = 3.4e38f;
        if (xl > 0)        dbx = fminf(dbx, gx - (X0 + (float)xl * HX));
        if (xr < BINX-1)   dbx = fminf(dbx, (X0 + (float)(xr+1) * HX) - gx);
        if (yl > 0)        dby = fminf(dby, gy - (Y0 + (float)yl * HY));
        if (yr < BINY-1)   dby = fminf(dby, fmaxf(0.0f, (Y0 + (float)(yr+1) * HY) - gy));
        float dlb2 = fminf(fmaf(dbx, dbx, domY2), dby * dby);
        if (b2 < dlb2 - 1e-4f) break;
    }
    #undef SCAN_CELL

    float4 p0 = sm->srt[i0], p1 = sm->srt[i1], p2 = sm->srt[i2];
    float dx, dy;
    dx = p0.x - gx; dy = p0.y - gy;
    float dd0 = sqrtf(__fadd_rn(__fmul_rn(dx,dx), __fmul_rn(dy,dy)));
    dx = p1.x - gx; dy = p1.y - gy;
    float dd1 = sqrtf(__fadd_rn(__fmul_rn(dx,dx), __fmul_rn(dy,dy)));
    dx = p2.x - gx; dy = p2.y - gy;
    float dd2 = sqrtf(__fadd_rn(__fmul_rn(dx,dx), __fmul_rn(dy,dy)));
    float sum = __fadd_rn(__fadd_rn(dd0, dd1), dd2);
    float w0 = __fdiv_rn(dd0, sum);
    float w1 = __fdiv_rn(dd1, sum);
    float w2 = __fdiv_rn(dd2, sum);
    float interp = __fadd_rn(__fadd_rn(__fmul_rn(p0.w, w0), __fmul_rn(p1.w, w1)),
                             __fmul_rn(p2.w, w2));

    g_ft[b][jlon][ilat] = interp;

    __syncthreads();
    __threadfence();
    if (tid == 0) atomicAdd(&g_arrive[b], 1);
}

// ---------------------------------------------------------------------------
// SHT role
// ---------------------------------------------------------------------------
__device__ void sht_role(float* __restrict__ out, SmemSHT* sm,
                         int sbid, int tid) {
    int m = sbid % MMAX;
    int b = sbid / MMAX;
    int t = tid;

    if (t < NLON) sm->ctab[t] = cospif((float)t * (1.0f / 128.0f));
    if (t < 64) {
        int l = m + 1 + t;
        if (l < LMAX)
            sm->sa[t] = sqrtf((float)(4*l*l - 1) / (float)(l*l - m*m));
        int l2 = m + 2 + t;
        if (l2 < LMAX) {
            int lm = l2 - 1;
            sm->sbb[t] = sqrtf((float)(lm*lm - m*m) / (float)(4*lm*lm - 1));
        }
    }
    __syncthreads();

    if (t < 128) {
        int k = t;
        float tfrac = (float)k * (1.0f / 127.0f);
        float x = cospif(tfrac);
        float s = sinpif(tfrac);

        float c1 = cospif(2.0f * tfrac);
        float cprev = 1.0f, ccur = c1;
        float S = 0.0f;
        #pragma unroll 7
        for (int kk = 1; kk <= 63; kk++) {
            float coef = 2.0f * f_rcp((float)(4*kk*kk - 1));
            S = fmaf(coef, ccur, S);
            float cnext = fmaf(2.0f * c1, ccur, -cprev);
            cprev = ccur; ccur = cnext;
        }
        float w = (2.0f / 127.0f) * (1.0f - S);
        if (k == 0 || k == NLAT - 1) w *= 0.5f;

        float pr = 1.0f;
        for (int mm = 1; mm <= m; mm++)
            pr *= f_div((float)(2*mm + 1), (float)(2*mm));
        float pref = sqrtf(pr * (1.0f / (4.0f * PI_F)));

        float sgn = 1.0f, base = -s;
        int e = m;
        while (e) { if (e & 1) sgn *= base; base *= base; e >>= 1; }
        float pmm = pref * sgn;

        float* wrow = &sm->sW[k * LMAX];
        for (int l = 0; l < m; l++) wrow[l] = 0.0f;
        wrow[m] = pmm * w;
        if (m + 1 < LMAX) {
            float p2 = pmm;
            float p1 = sm->sa[0] * x * pmm;
            wrow[m+1] = p1 * w;
            for (int l = m + 2; l < LMAX; l++) {
                float p = sm->sa[l - m - 1] * (x * p1 - sm->sbb[l - m - 2] * p2);
                wrow[l] = p * w;
                p2 = p1; p1 = p;
            }
        }
    } else if (t == 511) {
        while (atomicAdd(&g_arrive[b], 0) < NN_BLOCKS / BATCH) __nanosleep(128);
        __threadfence();
    }
    __syncthreads();

    if (t >= 128 && t < 384) {
        int th = t - 128;
        int k = th & 127, half = th >> 7;
        const float* __restrict__ fp = &g_ft[b][half * 128][k];
        int base = (m * (half * 128)) & 255;
        float a0 = 0.f, a1 = 0.f;
        #pragma unroll 16
        for (int jj = 0; jj < 128; jj += 2) {
            float f0 = __ldg(&fp[(jj + 0) * NLAT]);
            float f1 = __ldg(&fp[(jj + 1) * NLAT]);
            int idx0 = (base + jj * m) & 255;
            int idx1 = (base + (jj + 1) * m) & 255;
            a0 = fmaf(f0, sm->ctab[idx0], a0);
            a1 = fmaf(f1, sm->ctab[idx1], a1);
        }
        sm->pf[half][k] = a0 + a1;
    }
    __syncthreads();
    if (t < NLAT)
        sm->fre[t] = (sm->pf[0][t] + sm->pf[1][t]) * (2.0f * PI_F / (float)NLON);
    __syncthreads();

    int g = t >> 6, l = t & 63;
    if (t < 256 && l < LMAX) {
        float p = 0.f;
        int k0 = g * 32;
        #pragma unroll 8
        for (int kk = k0; kk < k0 + 32; kk++)
            p = fmaf(sm->fre[kk], sm->sW[kk * LMAX + l], p);
        sm->ps[g][l] = p;
    }
    __syncthreads();
    if (t < LMAX)
        out[(b * LMAX + t) * MMAX + m] =
            (sm->ps[0][t] + sm->ps[1][t]) + (sm->ps[2][t] + sm->ps[3][t]);

    __syncthreads();
    if (t == 0) {
        __threadfence();
        int d = atomicAdd(&g_done, 1);
        if (d == SHT_BLOCKS - 1) {
            g_arrive[0] = 0;
            g_arrive[1] = 0;
            g_done = 0;
            __threadfence();
        }
    }
}

// ---------------------------------------------------------------------------
__global__ __launch_bounds__(512, 2) void k_all(const float* __restrict__ tgt,
                                                float* __restrict__ out) {
    __shared__ union { SmemNN nn; SmemSHT sht; } smem;
    int bid = blockIdx.x;
    int tid = threadIdx.x;
    if (bid < NN_BLOCKS) nn_role(tgt, &smem.nn, bid, tid);
    else                 sht_role(out, &smem.sht, bid - NN_BLOCKS, tid);
}

// ---------------------------------------------------------------------------
extern "C" void kernel_launch(void* const* d_in, const int* in_sizes, int n_in,
                              void* d_out, int out_size) {
    const float* tgt = (const float*)d_in[0];
    float* out = (float*)d_out;
    k_all<<<ALL_BLOCKS, 512>>>(tgt, out);
}